// round 4
// baseline (speedup 1.0000x reference)
#include <cuda_runtime.h>
#include <cstdint>

#define N_NODES 100000
#define N_EDGES 1600000
#define DIM 128

// Scratch for the pre-transformed features y = x @ W^T  (51.2 MB)
__device__ float g_y[(size_t)N_NODES * DIM];

// ---------------------------------------------------------------------------
// Kernel 1: y = x @ W^T   (x: [N,128] row-major, W: [128,128] row-major [out][in])
// Tiled f32 SIMT GEMM. Block = 256 threads, BM=64 rows, full N=128 cols,
// k-tiles of 32. Each thread computes an 8x4 register tile.
// ---------------------------------------------------------------------------
constexpr int BM = 64;
constexpr int BK = 32;

__global__ __launch_bounds__(256) void gemm_kernel(const float* __restrict__ x,
                                                   const float* __restrict__ W) {
    __shared__ float sX[BM][BK];      // 8 KB
    __shared__ float sWt[BK][DIM];    // 16 KB, sWt[k][o] = W[o][kt+k]

    const int tid = threadIdx.x;
    const int tx  = tid & 31;         // col group: cols tx*4 .. tx*4+3
    const int ty  = tid >> 5;         // warp id: rows ty*8 .. ty*8+7
    const int row0 = blockIdx.x * BM;

    float acc[8][4];
#pragma unroll
    for (int r = 0; r < 8; r++)
#pragma unroll
        for (int c = 0; c < 4; c++) acc[r][c] = 0.f;

    for (int kt = 0; kt < DIM; kt += BK) {
        // --- load x tile: 64x32 floats = 512 float4, 2 per thread ---
#pragma unroll
        for (int i = 0; i < 2; i++) {
            int f  = tid + i * 256;         // float4 index 0..511
            int r  = f >> 3;                // 8 float4 per row
            int k4 = (f & 7) * 4;
            float4 v = make_float4(0.f, 0.f, 0.f, 0.f);
            int grow = row0 + r;
            if (grow < N_NODES)
                v = *(const float4*)(x + (size_t)grow * DIM + kt + k4);
            *(float4*)&sX[r][k4] = v;
        }
        // --- load W tile transposed: 128x32 floats = 1024 float4, 4 per thread ---
#pragma unroll
        for (int i = 0; i < 4; i++) {
            int f  = tid + i * 256;         // 0..1023
            int c  = f >> 3;                // output col (W row)
            int k4 = (f & 7) * 4;
            float4 v = *(const float4*)(W + (size_t)c * DIM + kt + k4);
            sWt[k4 + 0][c] = v.x;
            sWt[k4 + 1][c] = v.y;
            sWt[k4 + 2][c] = v.z;
            sWt[k4 + 3][c] = v.w;
        }
        __syncthreads();

#pragma unroll
        for (int kk = 0; kk < BK; kk++) {
            float4 wv = *(const float4*)&sWt[kk][tx * 4];
#pragma unroll
            for (int r = 0; r < 8; r++) {
                float xv = sX[ty * 8 + r][kk];   // warp-broadcast
                acc[r][0] += xv * wv.x;
                acc[r][1] += xv * wv.y;
                acc[r][2] += xv * wv.z;
                acc[r][3] += xv * wv.w;
            }
        }
        __syncthreads();
    }

#pragma unroll
    for (int r = 0; r < 8; r++) {
        int grow = row0 + ty * 8 + r;
        if (grow < N_NODES) {
            float4 v = make_float4(acc[r][0], acc[r][1], acc[r][2], acc[r][3]);
            *(float4*)(g_y + (size_t)grow * DIM + tx * 4) = v;
        }
    }
}

// ---------------------------------------------------------------------------
// Kernel 2: scatter  out[dst] += edge_attr * y[src]
// One warp per edge; each lane handles one float4 (32 lanes * 4 = 128 dims).
// edge_index is int32 (JAX x64-disabled downcasts int64 -> int32).
// red.global.add.v4.f32 -> 1 vector atomic per lane (51.2M total).
// ---------------------------------------------------------------------------
__global__ __launch_bounds__(256) void scatter_kernel(const int* __restrict__ ei,
                                                      const float* __restrict__ ea,
                                                      float* __restrict__ out) {
    const int e    = (int)(((size_t)blockIdx.x * 256 + threadIdx.x) >> 5);
    const int lane = threadIdx.x & 31;
    if (e >= N_EDGES) return;

    const int   s = __ldg(ei + e);             // source node
    const int   d = __ldg(ei + N_EDGES + e);   // target node
    const float a = __ldg(ea + e);

    float4 v = *(const float4*)(g_y + (size_t)s * DIM + lane * 4);
    v.x *= a; v.y *= a; v.z *= a; v.w *= a;

    float* p = out + (size_t)d * DIM + lane * 4;
    asm volatile("red.global.add.v4.f32 [%0], {%1, %2, %3, %4};"
                 :: "l"(p), "f"(v.x), "f"(v.y), "f"(v.z), "f"(v.w)
                 : "memory");
}

// ---------------------------------------------------------------------------
// Kernel 3: epilogue  out = leaky_relu(out + b)
// ---------------------------------------------------------------------------
__global__ __launch_bounds__(256) void epilogue_kernel(float* __restrict__ out,
                                                       const float* __restrict__ b) {
    size_t i = (size_t)blockIdx.x * 256 + threadIdx.x;   // float4 index
    if (i >= (size_t)N_NODES * DIM / 4) return;
    float4 v  = *(float4*)(out + i * 4);
    float4 bb = *(const float4*)(b + ((i * 4) & (DIM - 1)));
    v.x += bb.x; v.y += bb.y; v.z += bb.z; v.w += bb.w;
    v.x = v.x >= 0.f ? v.x : 0.01f * v.x;
    v.y = v.y >= 0.f ? v.y : 0.01f * v.y;
    v.z = v.z >= 0.f ? v.z : 0.01f * v.z;
    v.w = v.w >= 0.f ? v.w : 0.01f * v.w;
    *(float4*)(out + i * 4) = v;
}

// ---------------------------------------------------------------------------
extern "C" void kernel_launch(void* const* d_in, const int* in_sizes, int n_in,
                              void* d_out, int out_size) {
    const float* x  = (const float*)d_in[0];      // [100000, 128] f32
    const int*   ei = (const int*)d_in[1];        // [2, 1600000] i32
    const float* ea = (const float*)d_in[2];      // [1600000] f32
    const float* W  = (const float*)d_in[3];      // [128, 128] f32
    const float* b  = (const float*)d_in[4];      // [128] f32
    float*       out = (float*)d_out;             // [100000, 128] f32

    // Zero the accumulation buffer (d_out is poisoned before timing).
    cudaMemsetAsync(out, 0, (size_t)N_NODES * DIM * sizeof(float));

    // y = x @ W^T
    gemm_kernel<<<(N_NODES + BM - 1) / BM, 256>>>(x, W);

    // out[dst] += ea * y[src]
    scatter_kernel<<<(int)(((size_t)N_EDGES * 32 + 255) / 256), 256>>>(ei, ea, out);

    // out = leaky(out + b)
    epilogue_kernel<<<(int)(((size_t)N_NODES * DIM / 4 + 255) / 256), 256>>>(out, b);
}

// round 5
// speedup vs baseline: 1.0051x; 1.0051x over previous
#include <cuda_runtime.h>
#include <cstdint>

#define N_NODES 100000
#define N_EDGES 1600000
#define DIM 128

// Scratch for the pre-transformed features y = x @ W^T  (51.2 MB)
__device__ float g_y[(size_t)N_NODES * DIM];

// ---------------------------------------------------------------------------
// Kernel 1: y = x @ W^T   (x: [N,128] row-major, W: [128,128] row-major [out][in])
// Tiled f32 SIMT GEMM. Block = 256 threads, BM=64 rows, full 128 cols,
// k-tiles of 32. Each thread computes an 8x4 register tile.
// Inner loop unrolled by 4 over k with float4 LDS on BOTH operands:
// 12 LDS128 per 128 FFMA -> FFMA-issue bound instead of LDS-issue bound.
// ---------------------------------------------------------------------------
constexpr int BM = 64;
constexpr int BK = 32;

__global__ __launch_bounds__(256, 3) void gemm_kernel(const float* __restrict__ x,
                                                      const float* __restrict__ W) {
    __shared__ float sX[BM][BK];      // 8 KB
    __shared__ float sWt[BK][DIM];    // 16 KB, sWt[k][o] = W[o][kt+k]

    const int tid = threadIdx.x;
    const int tx  = tid & 31;         // col group: cols tx*4 .. tx*4+3
    const int ty  = tid >> 5;         // warp id: rows ty*8 .. ty*8+7
    const int row0 = blockIdx.x * BM;

    float4 acc[8];
#pragma unroll
    for (int r = 0; r < 8; r++) acc[r] = make_float4(0.f, 0.f, 0.f, 0.f);

    for (int kt = 0; kt < DIM; kt += BK) {
        // --- load x tile: 64x32 floats = 512 float4, 2 per thread ---
#pragma unroll
        for (int i = 0; i < 2; i++) {
            int f  = tid + i * 256;         // float4 index 0..511
            int r  = f >> 3;                // 8 float4 per row
            int k4 = (f & 7) * 4;
            float4 v = make_float4(0.f, 0.f, 0.f, 0.f);
            int grow = row0 + r;
            if (grow < N_NODES)
                v = *(const float4*)(x + (size_t)grow * DIM + kt + k4);
            *(float4*)&sX[r][k4] = v;
        }
        // --- load W tile transposed: 128x32 floats = 1024 float4, 4 per thread ---
#pragma unroll
        for (int i = 0; i < 4; i++) {
            int f  = tid + i * 256;         // 0..1023
            int c  = f >> 3;                // output col (W row)
            int k4 = (f & 7) * 4;
            float4 v = *(const float4*)(W + (size_t)c * DIM + kt + k4);
            sWt[k4 + 0][c] = v.x;
            sWt[k4 + 1][c] = v.y;
            sWt[k4 + 2][c] = v.z;
            sWt[k4 + 3][c] = v.w;
        }
        __syncthreads();

#pragma unroll
        for (int kk = 0; kk < BK; kk += 4) {
            float4 wv0 = *(const float4*)&sWt[kk + 0][tx * 4];
            float4 wv1 = *(const float4*)&sWt[kk + 1][tx * 4];
            float4 wv2 = *(const float4*)&sWt[kk + 2][tx * 4];
            float4 wv3 = *(const float4*)&sWt[kk + 3][tx * 4];
#pragma unroll
            for (int r = 0; r < 8; r++) {
                float4 xv = *(const float4*)&sX[ty * 8 + r][kk];  // warp-broadcast
                acc[r].x += xv.x * wv0.x; acc[r].y += xv.x * wv0.y;
                acc[r].z += xv.x * wv0.z; acc[r].w += xv.x * wv0.w;
                acc[r].x += xv.y * wv1.x; acc[r].y += xv.y * wv1.y;
                acc[r].z += xv.y * wv1.z; acc[r].w += xv.y * wv1.w;
                acc[r].x += xv.z * wv2.x; acc[r].y += xv.z * wv2.y;
                acc[r].z += xv.z * wv2.z; acc[r].w += xv.z * wv2.w;
                acc[r].x += xv.w * wv3.x; acc[r].y += xv.w * wv3.y;
                acc[r].z += xv.w * wv3.z; acc[r].w += xv.w * wv3.w;
            }
        }
        __syncthreads();
    }

#pragma unroll
    for (int r = 0; r < 8; r++) {
        int grow = row0 + ty * 8 + r;
        if (grow < N_NODES)
            *(float4*)(g_y + (size_t)grow * DIM + tx * 4) = acc[r];
    }
}

// ---------------------------------------------------------------------------
// Kernel 2: scatter  out[dst] += edge_attr * y[src]
// One warp per edge; each lane handles one float4 (32 lanes * 4 = 128 dims).
// edge_index is int32 (JAX x64-disabled downcasts int64 -> int32).
// red.global.add.v4.f32 -> 1 vector atomic per lane (51.2M total).
// ---------------------------------------------------------------------------
__global__ __launch_bounds__(256) void scatter_kernel(const int* __restrict__ ei,
                                                      const float* __restrict__ ea,
                                                      float* __restrict__ out) {
    const int e    = (int)(((size_t)blockIdx.x * 256 + threadIdx.x) >> 5);
    const int lane = threadIdx.x & 31;
    if (e >= N_EDGES) return;

    const int   s = __ldg(ei + e);             // source node
    const int   d = __ldg(ei + N_EDGES + e);   // target node
    const float a = __ldg(ea + e);

    float4 v = *(const float4*)(g_y + (size_t)s * DIM + lane * 4);
    v.x *= a; v.y *= a; v.z *= a; v.w *= a;

    float* p = out + (size_t)d * DIM + lane * 4;
    asm volatile("red.global.add.v4.f32 [%0], {%1, %2, %3, %4};"
                 :: "l"(p), "f"(v.x), "f"(v.y), "f"(v.z), "f"(v.w)
                 : "memory");
}

// ---------------------------------------------------------------------------
// Kernel 3: epilogue  out = leaky_relu(out + b)
// ---------------------------------------------------------------------------
__global__ __launch_bounds__(256) void epilogue_kernel(float* __restrict__ out,
                                                       const float* __restrict__ b) {
    size_t i = (size_t)blockIdx.x * 256 + threadIdx.x;   // float4 index
    if (i >= (size_t)N_NODES * DIM / 4) return;
    float4 v  = *(float4*)(out + i * 4);
    float4 bb = *(const float4*)(b + ((i * 4) & (DIM - 1)));
    v.x += bb.x; v.y += bb.y; v.z += bb.z; v.w += bb.w;
    v.x = v.x >= 0.f ? v.x : 0.01f * v.x;
    v.y = v.y >= 0.f ? v.y : 0.01f * v.y;
    v.z = v.z >= 0.f ? v.z : 0.01f * v.z;
    v.w = v.w >= 0.f ? v.w : 0.01f * v.w;
    *(float4*)(out + i * 4) = v;
}

// ---------------------------------------------------------------------------
extern "C" void kernel_launch(void* const* d_in, const int* in_sizes, int n_in,
                              void* d_out, int out_size) {
    const float* x  = (const float*)d_in[0];      // [100000, 128] f32
    const int*   ei = (const int*)d_in[1];        // [2, 1600000] i32
    const float* ea = (const float*)d_in[2];      // [1600000] f32
    const float* W  = (const float*)d_in[3];      // [128, 128] f32
    const float* b  = (const float*)d_in[4];      // [128] f32
    float*       out = (float*)d_out;             // [100000, 128] f32

    // Zero the accumulation buffer (d_out is poisoned before timing).
    cudaMemsetAsync(out, 0, (size_t)N_NODES * DIM * sizeof(float));

    // y = x @ W^T
    gemm_kernel<<<(N_NODES + BM - 1) / BM, 256>>>(x, W);

    // out[dst] += ea * y[src]
    scatter_kernel<<<(int)(((size_t)N_EDGES * 32 + 255) / 256), 256>>>(ei, ea, out);

    // out = leaky(out + b)
    epilogue_kernel<<<(int)(((size_t)N_NODES * DIM / 4 + 255) / 256), 256>>>(out, b);
}